// round 6
// baseline (speedup 1.0000x reference)
#include <cuda_runtime.h>
#include <math.h>
#include <stdint.h>

// HopAttentionLayer: B=256, T=64, N=2048, D=128
// attention[b,n] = softmax_n( 64 * <context[b,n,:], W[128:256]> )
// out[b,n,d] = attention[b,n] * context[b,n,d]
//
// Cluster-of-8, SMEM-resident tile: each CTA stages its 128KB slice in shared
// memory during the score pass, exchanges (max,sum) once via DSMEM, then
// scales from SMEM. Global traffic = read-once + write-once = 536 MB floor.

#define BDIM 512
static constexpr int Bsz  = 256;
static constexpr int Nctx = 2048;
static constexpr int Dd   = 128;
static constexpr int CS   = 8;            // CTAs per batch (cluster)
static constexpr int RS   = Nctx / CS;    // 256 rows per CTA
static constexpr int NWARP = BDIM / 32;   // 16

// dynamic smem layout (floats)
static constexpr int OFF_TILE  = 0;                    // RS*Dd = 32768
static constexpr int OFF_SCORE = RS * Dd;              // RS    = 256
static constexpr int OFF_RED   = OFF_SCORE + RS;       // NWARP = 16
static constexpr int OFF_PUB   = OFF_RED + NWARP;      // 2 (lmax, lsum)
static constexpr int OFF_GLB   = OFF_PUB + 2;          // 2 (gmax, ginv)
static constexpr int SMEM_FLOATS = OFF_GLB + 2;
static constexpr size_t SMEM_BYTES = SMEM_FLOATS * sizeof(float);

__device__ __forceinline__ uint32_t smem_u32(const void* p) {
    uint32_t a;
    asm("{ .reg .u64 t; cvta.to.shared.u64 t, %1; cvt.u32.u64 %0, t; }"
        : "=r"(a) : "l"(p));
    return a;
}
__device__ __forceinline__ float dsmem_ld_f32(uint32_t laddr, uint32_t rank) {
    uint32_t ra;
    asm("mapa.shared::cluster.u32 %0, %1, %2;" : "=r"(ra) : "r"(laddr), "r"(rank));
    float v;
    asm volatile("ld.shared::cluster.f32 %0, [%1];" : "=f"(v) : "r"(ra));
    return v;
}
#define CLUSTER_SYNC() do { \
    asm volatile("barrier.cluster.arrive.aligned;" ::: "memory"); \
    asm volatile("barrier.cluster.wait.aligned;"   ::: "memory"); \
} while (0)

__global__ __launch_bounds__(BDIM, 1) __cluster_dims__(CS, 1, 1)
void hop_attn_smem(const float* __restrict__ ctx,
                   const float* __restrict__ W,
                   float* __restrict__ out)
{
    extern __shared__ float sm[];
    float4*      tile4   = reinterpret_cast<float4*>(sm + OFF_TILE);
    float*       s_score = sm + OFF_SCORE;
    float*       s_red   = sm + OFF_RED;
    float*       s_pub   = sm + OFF_PUB;
    float*       s_glb   = sm + OFF_GLB;

    const int rank  = blockIdx.x;
    const int batch = blockIdx.y;
    const int tid   = threadIdx.x;
    const int warp  = tid >> 5;
    const int lane  = tid & 31;

    const float4 wc = *reinterpret_cast<const float4*>(W + Dd + lane * 4);

    const float4* c4 = reinterpret_cast<const float4*>(ctx)
                     + ((size_t)batch * Nctx + rank * RS) * (Dd / 4);
    float4*       o4 = reinterpret_cast<float4*>(out)
                     + ((size_t)batch * Nctx + rank * RS) * (Dd / 4);

    // ---- Pass 1: stream slice once: global -> (SMEM tile, dot products) ----
    #pragma unroll 4
    for (int k = 0; k < RS / NWARP; k++) {          // 16 iters, warp per row
        const int row = k * NWARP + warp;
        float4 v = c4[row * (Dd / 4) + lane];
        tile4[row * (Dd / 4) + lane] = v;
        float d = v.x * wc.x + v.y * wc.y + v.z * wc.z + v.w * wc.w;
        #pragma unroll
        for (int o = 16; o; o >>= 1) d += __shfl_xor_sync(0xffffffffu, d, o);
        if (lane == 0) s_score[row] = 64.0f * d;    // fold T=64
    }
    __syncthreads();

    // ---- Local max over RS=256 scores (threads 0..255) ----
    float m = (tid < RS) ? s_score[tid] : -INFINITY;
    #pragma unroll
    for (int o = 16; o; o >>= 1) m = fmaxf(m, __shfl_xor_sync(0xffffffffu, m, o));
    if (lane == 0) s_red[warp] = m;
    __syncthreads();
    if (warp == 0) {
        float mm = (lane < NWARP) ? s_red[lane] : -INFINITY;
        #pragma unroll
        for (int o = 8; o; o >>= 1) mm = fmaxf(mm, __shfl_xor_sync(0xffffffffu, mm, o));
        if (lane == 0) s_pub[0] = mm;
    }
    __syncthreads();
    const float lmax = s_pub[0];

    // ---- Local sum of exp(score - lmax) ----
    float e = (tid < RS) ? __expf(s_score[tid] - lmax) : 0.0f;
    float sum = e;
    #pragma unroll
    for (int o = 16; o; o >>= 1) sum += __shfl_xor_sync(0xffffffffu, sum, o);
    if (lane == 0) s_red[warp] = sum;
    __syncthreads();
    if (warp == 0) {
        float ss = (lane < NWARP) ? s_red[lane] : 0.0f;
        #pragma unroll
        for (int o = 8; o; o >>= 1) ss += __shfl_xor_sync(0xffffffffu, ss, o);
        if (lane == 0) s_pub[1] = ss;
    }
    CLUSTER_SYNC();   // single cluster exchange round

    // ---- Gather (m_i, s_i) from all 8 ranks; combine ----
    if (warp == 0) {
        const uint32_t aM = smem_u32(&s_pub[0]);
        const uint32_t aS = smem_u32(&s_pub[1]);
        float mi = -INFINITY, si = 0.0f;
        if (lane < CS) { mi = dsmem_ld_f32(aM, lane); si = dsmem_ld_f32(aS, lane); }
        float gm = mi;
        #pragma unroll
        for (int o = 4; o; o >>= 1) gm = fmaxf(gm, __shfl_xor_sync(0xffffffffu, gm, o));
        float contrib = (lane < CS) ? si * __expf(mi - gm) : 0.0f;
        #pragma unroll
        for (int o = 4; o; o >>= 1) contrib += __shfl_xor_sync(0xffffffffu, contrib, o);
        if (lane == 0) { s_glb[0] = gm; s_glb[1] = 1.0f / contrib; }
    }
    __syncthreads();
    const float gmax = s_glb[0];
    const float ginv = s_glb[1];

    // ---- Finalize probs in SMEM ----
    if (tid < RS) s_score[tid] = __expf(s_score[tid] - gmax) * ginv;
    __syncthreads();

    // ---- Pass 2: scale from SMEM tile, write out (no global re-read) ----
    constexpr int NV4 = RS * (Dd / 4);   // 8192 float4
    #pragma unroll 4
    for (int i = 0; i < NV4 / BDIM; i++) {
        const int idx = i * BDIM + tid;
        const float a = s_score[idx >> 5];      // uniform per warp
        float4 v = tile4[idx];
        v.x *= a; v.y *= a; v.z *= a; v.w *= a;
        o4[idx] = v;
    }

    // Peers may still be reading this CTA's s_pub via DSMEM — don't exit early.
    CLUSTER_SYNC();
}

extern "C" void kernel_launch(void* const* d_in, const int* in_sizes, int n_in,
                              void* d_out, int out_size)
{
    // d_in[0]=targetsentence_emb (unused), d_in[1]=context_emb, d_in[2]=W, d_in[3]=b (unused)
    const float* ctx = (const float*)d_in[1];
    const float* W   = (const float*)d_in[2];
    float* out       = (float*)d_out;

    cudaFuncSetAttribute(hop_attn_smem,
                         cudaFuncAttributeMaxDynamicSharedMemorySize,
                         (int)SMEM_BYTES);
    hop_attn_smem<<<dim3(CS, Bsz, 1), BDIM, SMEM_BYTES>>>(ctx, W, out);
}

// round 9
// speedup vs baseline: 1.1252x; 1.1252x over previous
#include <cuda_runtime.h>
#include <math.h>
#include <stdint.h>

// HopAttentionLayer: B=256, T=64, N=2048, D=128
// attention[b,n] = softmax_n( 64 * <context[b,n,:], W[128:256]> )
// out[b,n,d] = attention[b,n] * context[b,n,d]
//
// Cluster-of-8, SMEM-resident tile, 1024 threads/CTA (32 warps, occ 50%).
// Pass 1 streams the 128KB slice global->SMEM once while computing scores;
// one DSMEM exchange of (max,sum); pass 2 scales from SMEM and writes.
// DRAM traffic = read-once + write-once = 536 MB floor.

#define BDIM 1024
static constexpr int Bsz  = 256;
static constexpr int Nctx = 2048;
static constexpr int Dd   = 128;
static constexpr int CS   = 8;            // CTAs per batch (cluster)
static constexpr int RS   = Nctx / CS;    // 256 rows per CTA
static constexpr int NWARP = BDIM / 32;   // 32

// dynamic smem layout (floats)
static constexpr int OFF_TILE  = 0;                    // RS*Dd = 32768
static constexpr int OFF_SCORE = RS * Dd;              // RS    = 256
static constexpr int OFF_RED   = OFF_SCORE + RS;       // NWARP = 32
static constexpr int OFF_PUB   = OFF_RED + NWARP;      // 2 (lmax, lsum)
static constexpr int OFF_GLB   = OFF_PUB + 2;          // 2 (gmax, ginv)
static constexpr int SMEM_FLOATS = OFF_GLB + 2;
static constexpr size_t SMEM_BYTES = SMEM_FLOATS * sizeof(float);

__device__ __forceinline__ uint32_t smem_u32(const void* p) {
    uint32_t a;
    asm("{ .reg .u64 t; cvta.to.shared.u64 t, %1; cvt.u32.u64 %0, t; }"
        : "=r"(a) : "l"(p));
    return a;
}
__device__ __forceinline__ float dsmem_ld_f32(uint32_t laddr, uint32_t rank) {
    uint32_t ra;
    asm("mapa.shared::cluster.u32 %0, %1, %2;" : "=r"(ra) : "r"(laddr), "r"(rank));
    float v;
    asm volatile("ld.shared::cluster.f32 %0, [%1];" : "=f"(v) : "r"(ra));
    return v;
}
#define CLUSTER_SYNC() do { \
    asm volatile("barrier.cluster.arrive.aligned;" ::: "memory"); \
    asm volatile("barrier.cluster.wait.aligned;"   ::: "memory"); \
} while (0)

__global__ __launch_bounds__(BDIM, 1) __cluster_dims__(CS, 1, 1)
void hop_attn_smem(const float* __restrict__ ctx,
                   const float* __restrict__ W,
                   float* __restrict__ out)
{
    extern __shared__ float sm[];
    float4* tile4   = reinterpret_cast<float4*>(sm + OFF_TILE);
    float*  s_score = sm + OFF_SCORE;
    float*  s_red   = sm + OFF_RED;
    float*  s_pub   = sm + OFF_PUB;
    float*  s_glb   = sm + OFF_GLB;

    const int rank  = blockIdx.x;
    const int batch = blockIdx.y;
    const int tid   = threadIdx.x;
    const int warp  = tid >> 5;
    const int lane  = tid & 31;

    const float4 wc = *reinterpret_cast<const float4*>(W + Dd + lane * 4);

    const float4* c4 = reinterpret_cast<const float4*>(ctx)
                     + ((size_t)batch * Nctx + rank * RS) * (Dd / 4);
    float4*       o4 = reinterpret_cast<float4*>(out)
                     + ((size_t)batch * Nctx + rank * RS) * (Dd / 4);

    // ---- Pass 1: stream slice once: global -> (SMEM tile, dot products) ----
    // 8 rows per warp, fully unrolled: 8 independent LDG.128 batched up front.
    {
        constexpr int KPW = RS / NWARP;   // 8
        float4 v[KPW];
        #pragma unroll
        for (int k = 0; k < KPW; k++) {
            const int row = k * NWARP + warp;      // contiguous 16KB window per step
            v[k] = __ldcs(&c4[row * (Dd / 4) + lane]);   // single-use: evict-first
        }
        #pragma unroll
        for (int k = 0; k < KPW; k++) {
            const int row = k * NWARP + warp;
            tile4[row * (Dd / 4) + lane] = v[k];
            float d = v[k].x * wc.x + v[k].y * wc.y + v[k].z * wc.z + v[k].w * wc.w;
            #pragma unroll
            for (int o = 16; o; o >>= 1) d += __shfl_xor_sync(0xffffffffu, d, o);
            if (lane == 0) s_score[row] = 64.0f * d;   // fold T=64
        }
    }
    __syncthreads();

    // ---- Local max over RS=256 scores (threads 0..255 hold one each) ----
    float m = (tid < RS) ? s_score[tid] : -INFINITY;
    #pragma unroll
    for (int o = 16; o; o >>= 1) m = fmaxf(m, __shfl_xor_sync(0xffffffffu, m, o));
    if (lane == 0) s_red[warp] = m;
    __syncthreads();
    if (warp == 0) {
        float mm = s_red[lane];                    // NWARP == 32
        #pragma unroll
        for (int o = 16; o; o >>= 1) mm = fmaxf(mm, __shfl_xor_sync(0xffffffffu, mm, o));
        if (lane == 0) s_pub[0] = mm;
    }
    __syncthreads();
    const float lmax = s_pub[0];

    // ---- Local sum of exp(score - lmax) ----
    float e = (tid < RS) ? __expf(s_score[tid] - lmax) : 0.0f;
    float sum = e;
    #pragma unroll
    for (int o = 16; o; o >>= 1) sum += __shfl_xor_sync(0xffffffffu, sum, o);
    if (lane == 0) s_red[warp] = sum;
    __syncthreads();
    if (warp == 0) {
        float ss = s_red[lane];
        #pragma unroll
        for (int o = 16; o; o >>= 1) ss += __shfl_xor_sync(0xffffffffu, ss, o);
        if (lane == 0) s_pub[1] = ss;
    }
    CLUSTER_SYNC();   // single cluster exchange round

    // ---- Gather (m_i, s_i) from all 8 ranks; combine ----
    if (warp == 0) {
        const uint32_t aM = smem_u32(&s_pub[0]);
        const uint32_t aS = smem_u32(&s_pub[1]);
        float mi = -INFINITY, si = 0.0f;
        if (lane < CS) { mi = dsmem_ld_f32(aM, lane); si = dsmem_ld_f32(aS, lane); }
        float gm = mi;
        #pragma unroll
        for (int o = 4; o; o >>= 1) gm = fmaxf(gm, __shfl_xor_sync(0xffffffffu, gm, o));
        float contrib = (lane < CS) ? si * __expf(mi - gm) : 0.0f;
        #pragma unroll
        for (int o = 4; o; o >>= 1) contrib += __shfl_xor_sync(0xffffffffu, contrib, o);
        if (lane == 0) { s_glb[0] = gm; s_glb[1] = 1.0f / contrib; }
    }
    __syncthreads();
    const float gmax = s_glb[0];
    const float ginv = s_glb[1];

    // ---- Finalize probs in SMEM ----
    if (tid < RS) s_score[tid] = __expf(s_score[tid] - gmax) * ginv;
    __syncthreads();

    // ---- Pass 2: scale from SMEM tile, write out (no global re-read) ----
    constexpr int NV4 = RS * (Dd / 4);   // 8192 float4
    #pragma unroll
    for (int i = 0; i < NV4 / BDIM; i++) {   // 8 iters
        const int idx = i * BDIM + tid;
        const float a = s_score[idx >> 5];   // 32 float4 per row -> uniform per warp
        float4 v = tile4[idx];
        v.x *= a; v.y *= a; v.z *= a; v.w *= a;
        __stcs(&o4[idx], v);                 // streaming store: don't pollute L2
    }

    // Peers may still be reading this CTA's s_pub via DSMEM — don't exit early.
    CLUSTER_SYNC();
}

extern "C" void kernel_launch(void* const* d_in, const int* in_sizes, int n_in,
                              void* d_out, int out_size)
{
    // d_in[0]=targetsentence_emb (unused), d_in[1]=context_emb, d_in[2]=W, d_in[3]=b (unused)
    const float* ctx = (const float*)d_in[1];
    const float* W   = (const float*)d_in[2];
    float* out       = (float*)d_out;

    cudaFuncSetAttribute(hop_attn_smem,
                         cudaFuncAttributeMaxDynamicSharedMemorySize,
                         (int)SMEM_BYTES);
    hop_attn_smem<<<dim3(CS, Bsz, 1), BDIM, SMEM_BYTES>>>(ctx, W, out);
}

// round 10
// speedup vs baseline: 1.2207x; 1.0849x over previous
#include <cuda_runtime.h>
#include <math.h>
#include <stdint.h>

// HopAttentionLayer: B=256, T=64, N=2048, D=128
// attention[b,n] = softmax_n( 64 * <context[b,n,:], W[128:256]> )
// out[b,n,d] = attention[b,n] * context[b,n,d]
//
// Cluster-of-8 (128KB slice per CTA), occupancy capped at 2 CTAs/SM via a
// dummy dynamic-SMEM allocation. Pass 1 reads the slice (allocating in L2),
// one DSMEM exchange for the global softmax stats, pass 2 re-reads the slice
// from L2 (live footprint ~76MB < 126MB LTS) and streams the output with
// evict-first stores. DRAM traffic = read-once + write-once = 536 MB floor,
// with no phase serialization (co-resident CTAs are in different clusters).

#define BDIM 512
static constexpr int Bsz  = 256;
static constexpr int Nctx = 2048;
static constexpr int Dd   = 128;
static constexpr int CS   = 8;            // CTAs per batch (cluster)
static constexpr int RS   = Nctx / CS;    // 256 rows per CTA
static constexpr int NWARP = BDIM / 32;   // 16

// dynamic smem: first few floats used, rest is padding to cap occupancy at 2
static constexpr int OFF_SCORE = 0;                 // RS = 256
static constexpr int OFF_RED   = OFF_SCORE + RS;    // NWARP
static constexpr int OFF_PUB   = OFF_RED + NWARP;   // 2 (lmax, lsum)
static constexpr int OFF_GLB   = OFF_PUB + 2;       // 2 (gmax, ginv)
static constexpr size_t SMEM_BYTES = 100 * 1024;    // 227KB/100KB -> 2 CTAs/SM

__device__ __forceinline__ uint32_t smem_u32(const void* p) {
    uint32_t a;
    asm("{ .reg .u64 t; cvta.to.shared.u64 t, %1; cvt.u32.u64 %0, t; }"
        : "=r"(a) : "l"(p));
    return a;
}
__device__ __forceinline__ float dsmem_ld_f32(uint32_t laddr, uint32_t rank) {
    uint32_t ra;
    asm("mapa.shared::cluster.u32 %0, %1, %2;" : "=r"(ra) : "r"(laddr), "r"(rank));
    float v;
    asm volatile("ld.shared::cluster.f32 %0, [%1];" : "=f"(v) : "r"(ra));
    return v;
}
#define CLUSTER_SYNC() do { \
    asm volatile("barrier.cluster.arrive.aligned;" ::: "memory"); \
    asm volatile("barrier.cluster.wait.aligned;"   ::: "memory"); \
} while (0)

__global__ __launch_bounds__(BDIM, 1) __cluster_dims__(CS, 1, 1)
void hop_attn_l2(const float* __restrict__ ctx,
                 const float* __restrict__ W,
                 float* __restrict__ out)
{
    extern __shared__ float sm[];
    float* s_score = sm + OFF_SCORE;
    float* s_red   = sm + OFF_RED;
    float* s_pub   = sm + OFF_PUB;
    float* s_glb   = sm + OFF_GLB;

    const int rank  = blockIdx.x;
    const int batch = blockIdx.y;
    const int tid   = threadIdx.x;
    const int warp  = tid >> 5;
    const int lane  = tid & 31;

    const float4 wc = *reinterpret_cast<const float4*>(W + Dd + lane * 4);

    const float4* c4 = reinterpret_cast<const float4*>(ctx)
                     + ((size_t)batch * Nctx + rank * RS) * (Dd / 4);
    float4*       o4 = reinterpret_cast<float4*>(out)
                     + ((size_t)batch * Nctx + rank * RS) * (Dd / 4);

    // ---- Pass 1: scores; default load policy so the slice allocates in L2 ----
    // 16 rows per warp in two 8-deep batches (8 independent LDG.128 in flight).
    #pragma unroll
    for (int half = 0; half < 2; half++) {
        float4 v[8];
        #pragma unroll
        for (int k = 0; k < 8; k++) {
            const int row = (half * 8 + k) * NWARP + warp;  // contiguous 8KB/step
            v[k] = c4[row * (Dd / 4) + lane];
        }
        #pragma unroll
        for (int k = 0; k < 8; k++) {
            const int row = (half * 8 + k) * NWARP + warp;
            float d = v[k].x * wc.x + v[k].y * wc.y + v[k].z * wc.z + v[k].w * wc.w;
            #pragma unroll
            for (int o = 16; o; o >>= 1) d += __shfl_xor_sync(0xffffffffu, d, o);
            if (lane == 0) s_score[row] = 64.0f * d;   // fold T=64
        }
    }
    __syncthreads();

    // ---- Local max over RS=256 scores (threads 0..255) ----
    float m = (tid < RS) ? s_score[tid] : -INFINITY;
    #pragma unroll
    for (int o = 16; o; o >>= 1) m = fmaxf(m, __shfl_xor_sync(0xffffffffu, m, o));
    if (lane == 0) s_red[warp] = m;
    __syncthreads();
    if (warp == 0) {
        float mm = (lane < NWARP) ? s_red[lane] : -INFINITY;
        #pragma unroll
        for (int o = 8; o; o >>= 1) mm = fmaxf(mm, __shfl_xor_sync(0xffffffffu, mm, o));
        if (lane == 0) s_pub[0] = mm;
    }
    __syncthreads();
    const float lmax = s_pub[0];

    // ---- Local sum of exp(score - lmax) ----
    float e = (tid < RS) ? __expf(s_score[tid] - lmax) : 0.0f;
    float sum = e;
    #pragma unroll
    for (int o = 16; o; o >>= 1) sum += __shfl_xor_sync(0xffffffffu, sum, o);
    if (lane == 0) s_red[warp] = sum;
    __syncthreads();
    if (warp == 0) {
        float ss = (lane < NWARP) ? s_red[lane] : 0.0f;
        #pragma unroll
        for (int o = 8; o; o >>= 1) ss += __shfl_xor_sync(0xffffffffu, ss, o);
        if (lane == 0) s_pub[1] = ss;
    }
    CLUSTER_SYNC();   // publish (lmax, lsum) to cluster

    // ---- Gather (m_i, s_i) from all 8 ranks; combine ----
    if (warp == 0) {
        const uint32_t aM = smem_u32(&s_pub[0]);
        const uint32_t aS = smem_u32(&s_pub[1]);
        float mi = -INFINITY, si = 0.0f;
        if (lane < CS) { mi = dsmem_ld_f32(aM, lane); si = dsmem_ld_f32(aS, lane); }
        float gm = mi;
        #pragma unroll
        for (int o = 4; o; o >>= 1) gm = fmaxf(gm, __shfl_xor_sync(0xffffffffu, gm, o));
        float contrib = (lane < CS) ? si * __expf(mi - gm) : 0.0f;
        #pragma unroll
        for (int o = 4; o; o >>= 1) contrib += __shfl_xor_sync(0xffffffffu, contrib, o);
        if (lane == 0) { s_glb[0] = gm; s_glb[1] = 1.0f / contrib; }
    }
    // All DSMEM reads done after this point -> peers may exit freely later.
    CLUSTER_SYNC();
    __syncthreads();
    const float gmax = s_glb[0];
    const float ginv = s_glb[1];

    // ---- Finalize probs in SMEM ----
    if (tid < RS) s_score[tid] = __expf(s_score[tid] - gmax) * ginv;
    __syncthreads();

    // ---- Pass 2: re-read slice (L2 hit), scale, streaming store ----
    constexpr int NV4 = RS * (Dd / 4);   // 8192 float4
    #pragma unroll 4
    for (int i = 0; i < NV4 / BDIM; i++) {   // 16 iters
        const int idx = i * BDIM + tid;
        const float a = s_score[idx >> 5];   // 32 float4 per row -> uniform per warp
        float4 v = c4[idx];
        v.x *= a; v.y *= a; v.z *= a; v.w *= a;
        __stcs(&o4[idx], v);                 // evict-first: protect cached reads
    }
}

extern "C" void kernel_launch(void* const* d_in, const int* in_sizes, int n_in,
                              void* d_out, int out_size)
{
    // d_in[0]=targetsentence_emb (unused), d_in[1]=context_emb, d_in[2]=W, d_in[3]=b (unused)
    const float* ctx = (const float*)d_in[1];
    const float* W   = (const float*)d_in[2];
    float* out       = (float*)d_out;

    cudaFuncSetAttribute(hop_attn_l2,
                         cudaFuncAttributeMaxDynamicSharedMemorySize,
                         (int)SMEM_BYTES);
    hop_attn_l2<<<dim3(CS, Bsz, 1), BDIM, SMEM_BYTES>>>(ctx, W, out);
}

// round 13
// speedup vs baseline: 1.4222x; 1.1651x over previous
#include <cuda_runtime.h>
#include <math.h>
#include <stdint.h>

// HopAttentionLayer: B=256, T=64, N=2048, D=128
// attention[b,n] = softmax_n( 64 * <context[b,n,:], W[128:256]> )
// out[b,n,d] = attention[b,n] * context[b,n,d]
//
// Cluster-of-8 (128KB slice per CTA), exactly 2 CTAs/SM (launch_bounds regs<=64
// + 100KB dummy dynamic SMEM). Pass 1 reads the slice (allocates in L2, live
// footprint ~2*148*128KB = 38MB < 126MB LTS), one DSMEM exchange for global
// softmax stats, pass 2 re-reads from L2 and streams output with evict-first
// stores. DRAM traffic = 536 MB floor; co-resident CTAs are in different
// clusters so their phases interleave and memory stays busy.

#define BDIM 512
static constexpr int Bsz  = 256;
static constexpr int Nctx = 2048;
static constexpr int Dd   = 128;
static constexpr int CS   = 8;            // CTAs per batch (cluster)
static constexpr int RS   = Nctx / CS;    // 256 rows per CTA
static constexpr int NWARP = BDIM / 32;   // 16

// dynamic smem: first few floats used, rest pads occupancy to exactly 2 CTAs/SM
static constexpr int OFF_SCORE = 0;                 // RS = 256
static constexpr int OFF_RED   = OFF_SCORE + RS;    // NWARP
static constexpr int OFF_PUB   = OFF_RED + NWARP;   // 2 (lmax, lsum)
static constexpr int OFF_GLB   = OFF_PUB + 2;       // 2 (gmax, ginv)
static constexpr size_t SMEM_BYTES = 100 * 1024;    // 2 x 100KB < 228KB/SM

__device__ __forceinline__ uint32_t smem_u32(const void* p) {
    uint32_t a;
    asm("{ .reg .u64 t; cvta.to.shared.u64 t, %1; cvt.u32.u64 %0, t; }"
        : "=r"(a) : "l"(p));
    return a;
}
__device__ __forceinline__ float dsmem_ld_f32(uint32_t laddr, uint32_t rank) {
    uint32_t ra;
    asm("mapa.shared::cluster.u32 %0, %1, %2;" : "=r"(ra) : "r"(laddr), "r"(rank));
    float v;
    asm volatile("ld.shared::cluster.f32 %0, [%1];" : "=f"(v) : "r"(ra));
    return v;
}
#define CLUSTER_SYNC() do { \
    asm volatile("barrier.cluster.arrive.aligned;" ::: "memory"); \
    asm volatile("barrier.cluster.wait.aligned;"   ::: "memory"); \
} while (0)

__global__ __launch_bounds__(BDIM, 2) __cluster_dims__(CS, 1, 1)
void hop_attn_l2(const float* __restrict__ ctx,
                 const float* __restrict__ W,
                 float* __restrict__ out)
{
    extern __shared__ float sm[];
    float* s_score = sm + OFF_SCORE;
    float* s_red   = sm + OFF_RED;
    float* s_pub   = sm + OFF_PUB;
    float* s_glb   = sm + OFF_GLB;

    const int rank  = blockIdx.x;
    const int batch = blockIdx.y;
    const int tid   = threadIdx.x;
    const int warp  = tid >> 5;
    const int lane  = tid & 31;

    const float4 wc = *reinterpret_cast<const float4*>(W + Dd + lane * 4);

    const float4* c4 = reinterpret_cast<const float4*>(ctx)
                     + ((size_t)batch * Nctx + rank * RS) * (Dd / 4);
    float4*       o4 = reinterpret_cast<float4*>(out)
                     + ((size_t)batch * Nctx + rank * RS) * (Dd / 4);

    // ---- Pass 1: scores; default load policy so the slice allocates in L2 ----
    // 16 rows per warp in four 4-deep batches (4 independent LDG.128 in flight;
    // keeps regs <= 64 so 2 CTAs/SM stay resident).
    #pragma unroll
    for (int q = 0; q < 4; q++) {
        float4 v[4];
        #pragma unroll
        for (int k = 0; k < 4; k++) {
            const int row = (q * 4 + k) * NWARP + warp;   // contiguous 8KB/step
            v[k] = c4[row * (Dd / 4) + lane];
        }
        #pragma unroll
        for (int k = 0; k < 4; k++) {
            const int row = (q * 4 + k) * NWARP + warp;
            float d = v[k].x * wc.x + v[k].y * wc.y + v[k].z * wc.z + v[k].w * wc.w;
            #pragma unroll
            for (int o = 16; o; o >>= 1) d += __shfl_xor_sync(0xffffffffu, d, o);
            if (lane == 0) s_score[row] = 64.0f * d;   // fold T=64
        }
    }
    __syncthreads();

    // ---- Local max over RS=256 scores (threads 0..255) ----
    float m = (tid < RS) ? s_score[tid] : -INFINITY;
    #pragma unroll
    for (int o = 16; o; o >>= 1) m = fmaxf(m, __shfl_xor_sync(0xffffffffu, m, o));
    if (lane == 0) s_red[warp] = m;
    __syncthreads();
    if (warp == 0) {
        float mm = (lane < NWARP) ? s_red[lane] : -INFINITY;
        #pragma unroll
        for (int o = 8; o; o >>= 1) mm = fmaxf(mm, __shfl_xor_sync(0xffffffffu, mm, o));
        if (lane == 0) s_pub[0] = mm;
    }
    __syncthreads();
    const float lmax = s_pub[0];

    // ---- Local sum of exp(score - lmax) ----
    float e = (tid < RS) ? __expf(s_score[tid] - lmax) : 0.0f;
    float sum = e;
    #pragma unroll
    for (int o = 16; o; o >>= 1) sum += __shfl_xor_sync(0xffffffffu, sum, o);
    if (lane == 0) s_red[warp] = sum;
    __syncthreads();
    if (warp == 0) {
        float ss = (lane < NWARP) ? s_red[lane] : 0.0f;
        #pragma unroll
        for (int o = 8; o; o >>= 1) ss += __shfl_xor_sync(0xffffffffu, ss, o);
        if (lane == 0) s_pub[1] = ss;
    }
    CLUSTER_SYNC();   // publish (lmax, lsum) to cluster

    // ---- Gather (m_i, s_i) from all 8 ranks; combine ----
    if (warp == 0) {
        const uint32_t aM = smem_u32(&s_pub[0]);
        const uint32_t aS = smem_u32(&s_pub[1]);
        float mi = -INFINITY, si = 0.0f;
        if (lane < CS) { mi = dsmem_ld_f32(aM, lane); si = dsmem_ld_f32(aS, lane); }
        float gm = mi;
        #pragma unroll
        for (int o = 4; o; o >>= 1) gm = fmaxf(gm, __shfl_xor_sync(0xffffffffu, gm, o));
        float contrib = (lane < CS) ? si * __expf(mi - gm) : 0.0f;
        #pragma unroll
        for (int o = 4; o; o >>= 1) contrib += __shfl_xor_sync(0xffffffffu, contrib, o);
        if (lane == 0) { s_glb[0] = gm; s_glb[1] = 1.0f / contrib; }
    }
    // After this sync no rank touches peer SMEM -> free to exit after pass 2.
    CLUSTER_SYNC();
    __syncthreads();
    const float gmax = s_glb[0];
    const float ginv = s_glb[1];

    // ---- Finalize probs in SMEM ----
    if (tid < RS) s_score[tid] = __expf(s_score[tid] - gmax) * ginv;
    __syncthreads();

    // ---- Pass 2: re-read slice (L2 hit), scale, streaming store ----
    constexpr int NV4 = RS * (Dd / 4);   // 8192 float4
    #pragma unroll 4
    for (int i = 0; i < NV4 / BDIM; i++) {   // 16 iters
        const int idx = i * BDIM + tid;
        const float a = s_score[idx >> 5];   // 32 float4 per row -> uniform per warp
        float4 v = c4[idx];
        v.x *= a; v.y *= a; v.z *= a; v.w *= a;
        __stcs(&o4[idx], v);                 // evict-first: protect cached reads
    }
}

extern "C" void kernel_launch(void* const* d_in, const int* in_sizes, int n_in,
                              void* d_out, int out_size)
{
    // d_in[0]=targetsentence_emb (unused), d_in[1]=context_emb, d_in[2]=W, d_in[3]=b (unused)
    const float* ctx = (const float*)d_in[1];
    const float* W   = (const float*)d_in[2];
    float* out       = (float*)d_out;

    cudaFuncSetAttribute(hop_attn_l2,
                         cudaFuncAttributeMaxDynamicSharedMemorySize,
                         (int)SMEM_BYTES);
    hop_attn_l2<<<dim3(CS, Bsz, 1), BDIM, SMEM_BYTES>>>(ctx, W, out);
}